// round 13
// baseline (speedup 1.0000x reference)
#include <cuda_runtime.h>
#include <cstdint>

#define N_NODES 100000
#define F_IN    128
#define F_OUT   64
#define N_EDGES 1600000

// Scratch: support = x @ W   (25.6 MB, static __device__ to satisfy alloc guards)
__device__ float g_support[(size_t)N_NODES * F_OUT];
__device__ int   g_idx_is64;

// ---------------------------------------------------------------------------
// Phase 0: detect whether edge index buffers are int64 or int32.
// If data is int32, reading it as int64 packs two random indices per word:
// value = lo + hi*2^32 with hi in [0,100000), so values are >= 2^32 almost
// surely within 64 samples. Deterministic for fixed inputs.
// ---------------------------------------------------------------------------
__global__ void detect_idx_dtype(const void* __restrict__ src) {
    const long long* q = (const long long*)src;
    int ok = 1;
    for (int i = 0; i < 64; i++) {
        long long v = q[i];
        if (v < 0 || v >= (long long)N_NODES) { ok = 0; break; }
    }
    g_idx_is64 = ok;
}

// ---------------------------------------------------------------------------
// Phase 1: support[row][col] = sum_k x[row][k] * w[k][col]
// Block = 64x4 threads, 4 rows per block, x rows staged in shared.
// Weight (32 KB) is read coalesced and stays hot in L1/L2.
// ---------------------------------------------------------------------------
__global__ __launch_bounds__(256)
void gemm_kernel(const float* __restrict__ x, const float* __restrict__ w) {
    __shared__ float xs[4][F_IN];
    const int col   = threadIdx.x;           // 0..63
    const int rloc  = threadIdx.y;           // 0..3
    const int rbase = blockIdx.x * 4;
    const int tid   = rloc * 64 + col;

    // cooperative load of 4 x-rows (512 floats) by 256 threads
    #pragma unroll
    for (int i = 0; i < 2; i++) {
        int e  = tid + i * 256;               // 0..511
        int r  = e >> 7;                      // /128
        int k  = e & 127;
        int gr = rbase + r;
        xs[r][k] = (gr < N_NODES) ? x[(size_t)gr * F_IN + k] : 0.0f;
    }
    __syncthreads();

    const int row = rbase + rloc;
    float acc = 0.0f;
    #pragma unroll
    for (int k = 0; k < F_IN; k++)
        acc = fmaf(xs[rloc][k], w[k * F_OUT + col], acc);

    if (row < N_NODES)
        g_support[(size_t)row * F_OUT + col] = acc;
}

// ---------------------------------------------------------------------------
// Phase 2: out[dst] += val * support[src]
// 16 threads per edge; each thread: one float4 gather + 4 atomic adds.
// Gather rows are L2-resident (support = 25.6 MB < 126 MB L2).
// ---------------------------------------------------------------------------
__global__ __launch_bounds__(256)
void scatter_kernel(const float* __restrict__ edge_val,
                    const void*  __restrict__ edge_src,
                    const void*  __restrict__ edge_dst,
                    float* __restrict__ out) {
    const int t    = blockIdx.x * blockDim.x + threadIdx.x;
    const int edge = t >> 4;
    const int lane = t & 15;
    if (edge >= N_EDGES) return;

    int s, d;
    if (g_idx_is64) {
        s = (int)((const long long*)edge_src)[edge];
        d = (int)((const long long*)edge_dst)[edge];
    } else {
        s = ((const int*)edge_src)[edge];
        d = ((const int*)edge_dst)[edge];
    }
    const float v = edge_val[edge];

    const float4 m = ((const float4*)(g_support + (size_t)s * F_OUT))[lane];
    float* op = out + (size_t)d * F_OUT + lane * 4;
    atomicAdd(op + 0, m.x * v);
    atomicAdd(op + 1, m.y * v);
    atomicAdd(op + 2, m.z * v);
    atomicAdd(op + 3, m.w * v);
}

// ---------------------------------------------------------------------------
// Phase 3: in-place ReLU on out
// ---------------------------------------------------------------------------
__global__ __launch_bounds__(256)
void relu_kernel(float4* __restrict__ out, int n4) {
    int i = blockIdx.x * blockDim.x + threadIdx.x;
    if (i >= n4) return;
    float4 v = out[i];
    v.x = fmaxf(v.x, 0.0f);
    v.y = fmaxf(v.y, 0.0f);
    v.z = fmaxf(v.z, 0.0f);
    v.w = fmaxf(v.w, 0.0f);
    out[i] = v;
}

extern "C" void kernel_launch(void* const* d_in, const int* in_sizes, int n_in,
                              void* d_out, int out_size) {
    const float* x  = (const float*)d_in[0];   // [N_NODES, F_IN]
    const float* w  = (const float*)d_in[1];   // [F_IN, F_OUT]
    const float* ev = (const float*)d_in[2];   // [N_EDGES]
    const void*  es = d_in[3];                 // [N_EDGES] int64 or int32
    const void*  ed = d_in[4];                 // [N_EDGES] int64 or int32
    float* out = (float*)d_out;                // [N_NODES, F_OUT], poisoned

    // zero-init the accumulation target (graph-capturable async memset)
    cudaMemsetAsync(out, 0, (size_t)out_size * sizeof(float));

    detect_idx_dtype<<<1, 1>>>(es);

    dim3 gemm_block(64, 4);
    gemm_kernel<<<(N_NODES + 3) / 4, gemm_block>>>(x, w);

    const long long scat_threads = (long long)N_EDGES * 16;
    scatter_kernel<<<(int)((scat_threads + 255) / 256), 256>>>(ev, es, ed, out);

    const int n4 = out_size / 4;
    relu_kernel<<<(n4 + 255) / 256, 256>>>((float4*)out, n4);
}

// round 14
// speedup vs baseline: 2.6637x; 2.6637x over previous
#include <cuda_runtime.h>
#include <cstdint>

#define N_NODES 100000
#define F_IN    128
#define F_OUT   64
#define N_EDGES 1600000
#define SCAN_BLK 256
#define N_SCAN_BLKS ((N_NODES + SCAN_BLK - 1) / SCAN_BLK)   // 391

// ---- static scratch (alloc-free rule) ----
__device__ float g_support[(size_t)N_NODES * F_OUT];   // x @ W
__device__ int   g_idx_is64;
__device__ int   g_count[N_NODES];
__device__ int   g_row_start[N_NODES];                 // exclusive CSR offsets
__device__ int   g_cursor[N_NODES];
__device__ int   g_blocksum[N_SCAN_BLKS];

struct alignas(8) Edge { int src; float val; };
__device__ Edge  g_edges[N_EDGES];                     // dst-binned (src, val)

// ---------------------------------------------------------------------------
// Phase 0: int64 vs int32 index dtype probe (deterministic for fixed input)
// ---------------------------------------------------------------------------
__global__ void detect_idx_dtype(const void* __restrict__ src) {
    const long long* q = (const long long*)src;
    int ok = 1;
    for (int i = 0; i < 64; i++) {
        long long v = q[i];
        if (v < 0 || v >= (long long)N_NODES) { ok = 0; break; }
    }
    g_idx_is64 = ok;
}

__device__ __forceinline__ int load_idx(const void* p, int e) {
    return g_idx_is64 ? (int)((const long long*)p)[e] : ((const int*)p)[e];
}

// ---------------------------------------------------------------------------
// Phase 1: support = x @ W   (same shared-staged kernel as R13, ~25 us)
// ---------------------------------------------------------------------------
__global__ __launch_bounds__(256)
void gemm_kernel(const float* __restrict__ x, const float* __restrict__ w) {
    __shared__ float xs[4][F_IN];
    const int col   = threadIdx.x;           // 0..63
    const int rloc  = threadIdx.y;           // 0..3
    const int rbase = blockIdx.x * 4;
    const int tid   = rloc * 64 + col;

    #pragma unroll
    for (int i = 0; i < 2; i++) {
        int e  = tid + i * 256;
        int r  = e >> 7;
        int k  = e & 127;
        int gr = rbase + r;
        xs[r][k] = (gr < N_NODES) ? x[(size_t)gr * F_IN + k] : 0.0f;
    }
    __syncthreads();

    const int row = rbase + rloc;
    float acc = 0.0f;
    #pragma unroll
    for (int k = 0; k < F_IN; k++)
        acc = fmaf(xs[rloc][k], w[k * F_OUT + col], acc);

    if (row < N_NODES)
        g_support[(size_t)row * F_OUT + col] = acc;
}

// ---------------------------------------------------------------------------
// Phase 2a: zero counters, histogram of dst
// ---------------------------------------------------------------------------
__global__ __launch_bounds__(256)
void zero_counts() {
    int i = blockIdx.x * blockDim.x + threadIdx.x;
    if (i < N_NODES) g_count[i] = 0;
}

__global__ __launch_bounds__(256)
void hist_kernel(const void* __restrict__ ed) {
    int e = blockIdx.x * blockDim.x + threadIdx.x;
    if (e >= N_EDGES) return;
    atomicAdd(&g_count[load_idx(ed, e)], 1);
}

// ---------------------------------------------------------------------------
// Phase 2b: 3-kernel exclusive scan of counts -> row_start, cursor
// ---------------------------------------------------------------------------
__global__ __launch_bounds__(SCAN_BLK)
void scan1() {
    __shared__ int sh[SCAN_BLK];
    int i = blockIdx.x * SCAN_BLK + threadIdx.x;
    int v = (i < N_NODES) ? g_count[i] : 0;
    sh[threadIdx.x] = v;
    __syncthreads();
    for (int off = 1; off < SCAN_BLK; off <<= 1) {
        int t = (threadIdx.x >= off) ? sh[threadIdx.x - off] : 0;
        __syncthreads();
        sh[threadIdx.x] += t;
        __syncthreads();
    }
    if (i < N_NODES) g_row_start[i] = sh[threadIdx.x] - v;   // exclusive in-block
    if (threadIdx.x == SCAN_BLK - 1) g_blocksum[blockIdx.x] = sh[SCAN_BLK - 1];
}

__global__ __launch_bounds__(512)
void scan2() {
    __shared__ int sh[512];
    int i = threadIdx.x;
    int v = (i < N_SCAN_BLKS) ? g_blocksum[i] : 0;
    sh[i] = v;
    __syncthreads();
    for (int off = 1; off < 512; off <<= 1) {
        int t = (i >= off) ? sh[i - off] : 0;
        __syncthreads();
        sh[i] += t;
        __syncthreads();
    }
    if (i < N_SCAN_BLKS) g_blocksum[i] = sh[i] - v;          // exclusive
}

__global__ __launch_bounds__(SCAN_BLK)
void scan3() {
    int i = blockIdx.x * SCAN_BLK + threadIdx.x;
    if (i >= N_NODES) return;
    int rs = g_row_start[i] + g_blocksum[blockIdx.x];
    g_row_start[i] = rs;
    g_cursor[i]    = rs;
}

// ---------------------------------------------------------------------------
// Phase 2c: scatter edges into dst bins (packed 8B records)
// ---------------------------------------------------------------------------
__global__ __launch_bounds__(256)
void fill_kernel(const float* __restrict__ ev,
                 const void*  __restrict__ es,
                 const void*  __restrict__ ed) {
    int e = blockIdx.x * blockDim.x + threadIdx.x;
    if (e >= N_EDGES) return;
    int d   = load_idx(ed, e);
    int pos = atomicAdd(&g_cursor[d], 1);
    Edge eg;
    eg.src = load_idx(es, e);
    eg.val = ev[e];
    g_edges[pos] = eg;
}

// ---------------------------------------------------------------------------
// Phase 3: per-node aggregation. 1 warp/node, lane owns 2 features.
// Edge records broadcast via shfl; ReLU fused; no output atomics.
// ---------------------------------------------------------------------------
__global__ __launch_bounds__(256)
void agg_kernel(float* __restrict__ out) {
    const int node = (blockIdx.x * blockDim.x + threadIdx.x) >> 5;
    const int lane = threadIdx.x & 31;
    if (node >= N_NODES) return;

    const int start = g_row_start[node];
    const int end   = (node + 1 < N_NODES) ? g_row_start[node + 1] : N_EDGES;

    float2 acc = make_float2(0.0f, 0.0f);
    for (int base = start; base < end; base += 32) {
        const int n = min(32, end - base);
        long long mybits = 0;
        if (lane < n) {
            Edge my = g_edges[base + lane];
            mybits = *(const long long*)&my;
        }
        for (int j = 0; j < n; j++) {
            long long b = __shfl_sync(0xffffffffu, mybits, j);
            Edge eg = *(const Edge*)&b;
            float2 m = ((const float2*)(g_support + (size_t)eg.src * F_OUT))[lane];
            acc.x = fmaf(m.x, eg.val, acc.x);
            acc.y = fmaf(m.y, eg.val, acc.y);
        }
    }
    float2 r = make_float2(fmaxf(acc.x, 0.0f), fmaxf(acc.y, 0.0f));
    ((float2*)(out + (size_t)node * F_OUT))[lane] = r;
}

extern "C" void kernel_launch(void* const* d_in, const int* in_sizes, int n_in,
                              void* d_out, int out_size) {
    const float* x  = (const float*)d_in[0];
    const float* w  = (const float*)d_in[1];
    const float* ev = (const float*)d_in[2];
    const void*  es = d_in[3];
    const void*  ed = d_in[4];
    float* out = (float*)d_out;

    detect_idx_dtype<<<1, 1>>>(es);

    dim3 gemm_block(64, 4);
    gemm_kernel<<<(N_NODES + 3) / 4, gemm_block>>>(x, w);

    zero_counts<<<(N_NODES + 255) / 256, 256>>>();
    hist_kernel<<<(N_EDGES + 255) / 256, 256>>>(ed);

    scan1<<<N_SCAN_BLKS, SCAN_BLK>>>();
    scan2<<<1, 512>>>();
    scan3<<<N_SCAN_BLKS, SCAN_BLK>>>();

    fill_kernel<<<(N_EDGES + 255) / 256, 256>>>(ev, es, ed);

    // 8 warps/block -> 8 nodes/block
    agg_kernel<<<(N_NODES + 7) / 8, 256>>>(out);
}

// round 15
// speedup vs baseline: 2.6677x; 1.0015x over previous
#include <cuda_runtime.h>
#include <cstdint>

#define N_NODES 100000
#define F_IN    128
#define F_OUT   64
#define N_EDGES 1600000
#define SCAN_BLK 256
#define N_SCAN_BLKS ((N_NODES + SCAN_BLK - 1) / SCAN_BLK)   // 391

// ---- static scratch (alloc-free rule) ----
__device__ float g_support[(size_t)N_NODES * F_OUT];   // x @ W
__device__ int   g_idx_is64;
__device__ int   g_count[N_NODES];
__device__ int   g_row_start[N_NODES];                 // exclusive CSR offsets
__device__ int   g_cursor[N_NODES];
__device__ int   g_blocksum[N_SCAN_BLKS];

struct alignas(8) Edge { int src; float val; };
__device__ Edge  g_edges[N_EDGES];                     // dst-binned (src, val)

// ---------------------------------------------------------------------------
// Phase 0: int64 vs int32 index dtype probe (deterministic for fixed input)
// ---------------------------------------------------------------------------
__global__ void detect_idx_dtype(const void* __restrict__ src) {
    const long long* q = (const long long*)src;
    int ok = 1;
    for (int i = 0; i < 64; i++) {
        long long v = q[i];
        if (v < 0 || v >= (long long)N_NODES) { ok = 0; break; }
    }
    g_idx_is64 = ok;
}

__device__ __forceinline__ int load_idx(const void* p, int e) {
    return g_idx_is64 ? (int)((const long long*)p)[e] : ((const int*)p)[e];
}

// ---------------------------------------------------------------------------
// Phase 1: support = x @ W   (same shared-staged kernel as R13, ~25 us)
// ---------------------------------------------------------------------------
__global__ __launch_bounds__(256)
void gemm_kernel(const float* __restrict__ x, const float* __restrict__ w) {
    __shared__ float xs[4][F_IN];
    const int col   = threadIdx.x;           // 0..63
    const int rloc  = threadIdx.y;           // 0..3
    const int rbase = blockIdx.x * 4;
    const int tid   = rloc * 64 + col;

    #pragma unroll
    for (int i = 0; i < 2; i++) {
        int e  = tid + i * 256;
        int r  = e >> 7;
        int k  = e & 127;
        int gr = rbase + r;
        xs[r][k] = (gr < N_NODES) ? x[(size_t)gr * F_IN + k] : 0.0f;
    }
    __syncthreads();

    const int row = rbase + rloc;
    float acc = 0.0f;
    #pragma unroll
    for (int k = 0; k < F_IN; k++)
        acc = fmaf(xs[rloc][k], w[k * F_OUT + col], acc);

    if (row < N_NODES)
        g_support[(size_t)row * F_OUT + col] = acc;
}

// ---------------------------------------------------------------------------
// Phase 2a: zero counters, histogram of dst
// ---------------------------------------------------------------------------
__global__ __launch_bounds__(256)
void zero_counts() {
    int i = blockIdx.x * blockDim.x + threadIdx.x;
    if (i < N_NODES) g_count[i] = 0;
}

__global__ __launch_bounds__(256)
void hist_kernel(const void* __restrict__ ed) {
    int e = blockIdx.x * blockDim.x + threadIdx.x;
    if (e >= N_EDGES) return;
    atomicAdd(&g_count[load_idx(ed, e)], 1);
}

// ---------------------------------------------------------------------------
// Phase 2b: 3-kernel exclusive scan of counts -> row_start, cursor
// ---------------------------------------------------------------------------
__global__ __launch_bounds__(SCAN_BLK)
void scan1() {
    __shared__ int sh[SCAN_BLK];
    int i = blockIdx.x * SCAN_BLK + threadIdx.x;
    int v = (i < N_NODES) ? g_count[i] : 0;
    sh[threadIdx.x] = v;
    __syncthreads();
    for (int off = 1; off < SCAN_BLK; off <<= 1) {
        int t = (threadIdx.x >= off) ? sh[threadIdx.x - off] : 0;
        __syncthreads();
        sh[threadIdx.x] += t;
        __syncthreads();
    }
    if (i < N_NODES) g_row_start[i] = sh[threadIdx.x] - v;   // exclusive in-block
    if (threadIdx.x == SCAN_BLK - 1) g_blocksum[blockIdx.x] = sh[SCAN_BLK - 1];
}

__global__ __launch_bounds__(512)
void scan2() {
    __shared__ int sh[512];
    int i = threadIdx.x;
    int v = (i < N_SCAN_BLKS) ? g_blocksum[i] : 0;
    sh[i] = v;
    __syncthreads();
    for (int off = 1; off < 512; off <<= 1) {
        int t = (i >= off) ? sh[i - off] : 0;
        __syncthreads();
        sh[i] += t;
        __syncthreads();
    }
    if (i < N_SCAN_BLKS) g_blocksum[i] = sh[i] - v;          // exclusive
}

__global__ __launch_bounds__(SCAN_BLK)
void scan3() {
    int i = blockIdx.x * SCAN_BLK + threadIdx.x;
    if (i >= N_NODES) return;
    int rs = g_row_start[i] + g_blocksum[blockIdx.x];
    g_row_start[i] = rs;
    g_cursor[i]    = rs;
}

// ---------------------------------------------------------------------------
// Phase 2c: scatter edges into dst bins (packed 8B records)
// ---------------------------------------------------------------------------
__global__ __launch_bounds__(256)
void fill_kernel(const float* __restrict__ ev,
                 const void*  __restrict__ es,
                 const void*  __restrict__ ed) {
    int e = blockIdx.x * blockDim.x + threadIdx.x;
    if (e >= N_EDGES) return;
    int d   = load_idx(ed, e);
    int pos = atomicAdd(&g_cursor[d], 1);
    Edge eg;
    eg.src = load_idx(es, e);
    eg.val = ev[e];
    g_edges[pos] = eg;
}

// ---------------------------------------------------------------------------
// Phase 3: per-node aggregation. 1 warp/node, lane owns 2 features.
// Edge records broadcast via shfl; ReLU fused; no output atomics.
// ---------------------------------------------------------------------------
__global__ __launch_bounds__(256)
void agg_kernel(float* __restrict__ out) {
    const int node = (blockIdx.x * blockDim.x + threadIdx.x) >> 5;
    const int lane = threadIdx.x & 31;
    if (node >= N_NODES) return;

    const int start = g_row_start[node];
    const int end   = (node + 1 < N_NODES) ? g_row_start[node + 1] : N_EDGES;

    float2 acc = make_float2(0.0f, 0.0f);
    for (int base = start; base < end; base += 32) {
        const int n = min(32, end - base);
        long long mybits = 0;
        if (lane < n) {
            Edge my = g_edges[base + lane];
            mybits = *(const long long*)&my;
        }
        for (int j = 0; j < n; j++) {
            long long b = __shfl_sync(0xffffffffu, mybits, j);
            Edge eg = *(const Edge*)&b;
            float2 m = ((const float2*)(g_support + (size_t)eg.src * F_OUT))[lane];
            acc.x = fmaf(m.x, eg.val, acc.x);
            acc.y = fmaf(m.y, eg.val, acc.y);
        }
    }
    float2 r = make_float2(fmaxf(acc.x, 0.0f), fmaxf(acc.y, 0.0f));
    ((float2*)(out + (size_t)node * F_OUT))[lane] = r;
}

extern "C" void kernel_launch(void* const* d_in, const int* in_sizes, int n_in,
                              void* d_out, int out_size) {
    const float* x  = (const float*)d_in[0];
    const float* w  = (const float*)d_in[1];
    const float* ev = (const float*)d_in[2];
    const void*  es = d_in[3];
    const void*  ed = d_in[4];
    float* out = (float*)d_out;

    detect_idx_dtype<<<1, 1>>>(es);

    dim3 gemm_block(64, 4);
    gemm_kernel<<<(N_NODES + 3) / 4, gemm_block>>>(x, w);

    zero_counts<<<(N_NODES + 255) / 256, 256>>>();
    hist_kernel<<<(N_EDGES + 255) / 256, 256>>>(ed);

    scan1<<<N_SCAN_BLKS, SCAN_BLK>>>();
    scan2<<<1, 512>>>();
    scan3<<<N_SCAN_BLKS, SCAN_BLK>>>();

    fill_kernel<<<(N_EDGES + 255) / 256, 256>>>(ev, es, ed);

    // 8 warps/block -> 8 nodes/block
    agg_kernel<<<(N_NODES + 7) / 8, 256>>>(out);
}

// round 16
// speedup vs baseline: 2.6685x; 1.0003x over previous
#include <cuda_runtime.h>
#include <cstdint>

#define N_NODES 100000
#define F_IN    128
#define F_OUT   64
#define N_EDGES 1600000
#define SCAN_BLK 256
#define N_SCAN_BLKS ((N_NODES + SCAN_BLK - 1) / SCAN_BLK)   // 391

// ---- static scratch (alloc-free rule) ----
__device__ float g_support[(size_t)N_NODES * F_OUT];   // x @ W
__device__ int   g_idx_is64;
__device__ int   g_count[N_NODES];
__device__ int   g_row_start[N_NODES];                 // exclusive CSR offsets
__device__ int   g_cursor[N_NODES];
__device__ int   g_blocksum[N_SCAN_BLKS];

struct alignas(8) Edge { int src; float val; };
__device__ Edge  g_edges[N_EDGES];                     // dst-binned (src, val)

// ---------------------------------------------------------------------------
// Phase 0: int64 vs int32 index dtype probe (deterministic for fixed input)
// ---------------------------------------------------------------------------
__global__ void detect_idx_dtype(const void* __restrict__ src) {
    const long long* q = (const long long*)src;
    int ok = 1;
    for (int i = 0; i < 64; i++) {
        long long v = q[i];
        if (v < 0 || v >= (long long)N_NODES) { ok = 0; break; }
    }
    g_idx_is64 = ok;
}

__device__ __forceinline__ int load_idx(const void* p, int e) {
    return g_idx_is64 ? (int)((const long long*)p)[e] : ((const int*)p)[e];
}

// ---------------------------------------------------------------------------
// Phase 1: support = x @ W   (same shared-staged kernel as R13, ~25 us)
// ---------------------------------------------------------------------------
__global__ __launch_bounds__(256)
void gemm_kernel(const float* __restrict__ x, const float* __restrict__ w) {
    __shared__ float xs[4][F_IN];
    const int col   = threadIdx.x;           // 0..63
    const int rloc  = threadIdx.y;           // 0..3
    const int rbase = blockIdx.x * 4;
    const int tid   = rloc * 64 + col;

    #pragma unroll
    for (int i = 0; i < 2; i++) {
        int e  = tid + i * 256;
        int r  = e >> 7;
        int k  = e & 127;
        int gr = rbase + r;
        xs[r][k] = (gr < N_NODES) ? x[(size_t)gr * F_IN + k] : 0.0f;
    }
    __syncthreads();

    const int row = rbase + rloc;
    float acc = 0.0f;
    #pragma unroll
    for (int k = 0; k < F_IN; k++)
        acc = fmaf(xs[rloc][k], w[k * F_OUT + col], acc);

    if (row < N_NODES)
        g_support[(size_t)row * F_OUT + col] = acc;
}

// ---------------------------------------------------------------------------
// Phase 2a: zero counters, histogram of dst
// ---------------------------------------------------------------------------
__global__ __launch_bounds__(256)
void zero_counts() {
    int i = blockIdx.x * blockDim.x + threadIdx.x;
    if (i < N_NODES) g_count[i] = 0;
}

__global__ __launch_bounds__(256)
void hist_kernel(const void* __restrict__ ed) {
    int e = blockIdx.x * blockDim.x + threadIdx.x;
    if (e >= N_EDGES) return;
    atomicAdd(&g_count[load_idx(ed, e)], 1);
}

// ---------------------------------------------------------------------------
// Phase 2b: 3-kernel exclusive scan of counts -> row_start, cursor
// ---------------------------------------------------------------------------
__global__ __launch_bounds__(SCAN_BLK)
void scan1() {
    __shared__ int sh[SCAN_BLK];
    int i = blockIdx.x * SCAN_BLK + threadIdx.x;
    int v = (i < N_NODES) ? g_count[i] : 0;
    sh[threadIdx.x] = v;
    __syncthreads();
    for (int off = 1; off < SCAN_BLK; off <<= 1) {
        int t = (threadIdx.x >= off) ? sh[threadIdx.x - off] : 0;
        __syncthreads();
        sh[threadIdx.x] += t;
        __syncthreads();
    }
    if (i < N_NODES) g_row_start[i] = sh[threadIdx.x] - v;   // exclusive in-block
    if (threadIdx.x == SCAN_BLK - 1) g_blocksum[blockIdx.x] = sh[SCAN_BLK - 1];
}

__global__ __launch_bounds__(512)
void scan2() {
    __shared__ int sh[512];
    int i = threadIdx.x;
    int v = (i < N_SCAN_BLKS) ? g_blocksum[i] : 0;
    sh[i] = v;
    __syncthreads();
    for (int off = 1; off < 512; off <<= 1) {
        int t = (i >= off) ? sh[i - off] : 0;
        __syncthreads();
        sh[i] += t;
        __syncthreads();
    }
    if (i < N_SCAN_BLKS) g_blocksum[i] = sh[i] - v;          // exclusive
}

__global__ __launch_bounds__(SCAN_BLK)
void scan3() {
    int i = blockIdx.x * SCAN_BLK + threadIdx.x;
    if (i >= N_NODES) return;
    int rs = g_row_start[i] + g_blocksum[blockIdx.x];
    g_row_start[i] = rs;
    g_cursor[i]    = rs;
}

// ---------------------------------------------------------------------------
// Phase 2c: scatter edges into dst bins (packed 8B records)
// ---------------------------------------------------------------------------
__global__ __launch_bounds__(256)
void fill_kernel(const float* __restrict__ ev,
                 const void*  __restrict__ es,
                 const void*  __restrict__ ed) {
    int e = blockIdx.x * blockDim.x + threadIdx.x;
    if (e >= N_EDGES) return;
    int d   = load_idx(ed, e);
    int pos = atomicAdd(&g_cursor[d], 1);
    Edge eg;
    eg.src = load_idx(es, e);
    eg.val = ev[e];
    g_edges[pos] = eg;
}

// ---------------------------------------------------------------------------
// Phase 3: per-node aggregation. 1 warp/node, lane owns 2 features.
// Edge records broadcast via shfl; ReLU fused; no output atomics.
// ---------------------------------------------------------------------------
__global__ __launch_bounds__(256)
void agg_kernel(float* __restrict__ out) {
    const int node = (blockIdx.x * blockDim.x + threadIdx.x) >> 5;
    const int lane = threadIdx.x & 31;
    if (node >= N_NODES) return;

    const int start = g_row_start[node];
    const int end   = (node + 1 < N_NODES) ? g_row_start[node + 1] : N_EDGES;

    float2 acc = make_float2(0.0f, 0.0f);
    for (int base = start; base < end; base += 32) {
        const int n = min(32, end - base);
        long long mybits = 0;
        if (lane < n) {
            Edge my = g_edges[base + lane];
            mybits = *(const long long*)&my;
        }
        for (int j = 0; j < n; j++) {
            long long b = __shfl_sync(0xffffffffu, mybits, j);
            Edge eg = *(const Edge*)&b;
            float2 m = ((const float2*)(g_support + (size_t)eg.src * F_OUT))[lane];
            acc.x = fmaf(m.x, eg.val, acc.x);
            acc.y = fmaf(m.y, eg.val, acc.y);
        }
    }
    float2 r = make_float2(fmaxf(acc.x, 0.0f), fmaxf(acc.y, 0.0f));
    ((float2*)(out + (size_t)node * F_OUT))[lane] = r;
}

extern "C" void kernel_launch(void* const* d_in, const int* in_sizes, int n_in,
                              void* d_out, int out_size) {
    const float* x  = (const float*)d_in[0];
    const float* w  = (const float*)d_in[1];
    const float* ev = (const float*)d_in[2];
    const void*  es = d_in[3];
    const void*  ed = d_in[4];
    float* out = (float*)d_out;

    detect_idx_dtype<<<1, 1>>>(es);

    dim3 gemm_block(64, 4);
    gemm_kernel<<<(N_NODES + 3) / 4, gemm_block>>>(x, w);

    zero_counts<<<(N_NODES + 255) / 256, 256>>>();
    hist_kernel<<<(N_EDGES + 255) / 256, 256>>>(ed);

    scan1<<<N_SCAN_BLKS, SCAN_BLK>>>();
    scan2<<<1, 512>>>();
    scan3<<<N_SCAN_BLKS, SCAN_BLK>>>();

    fill_kernel<<<(N_EDGES + 255) / 256, 256>>>(ev, es, ed);

    // 8 warps/block -> 8 nodes/block
    agg_kernel<<<(N_NODES + 7) / 8, 256>>>(out);
}